// round 2
// baseline (speedup 1.0000x reference)
#include <cuda_runtime.h>
#include <float.h>

// Problem constants
#define B_   16
#define C_   64
#define H_   256
#define W_   256
#define OC_  128
#define OH_  254
#define OW_  254

// Tiling
#define TB   128      // threads per block
#define TX   64       // output tile width
#define TY   16       // output tile height
#define ICC  8        // input-channel chunk staged in smem
#define G    8        // output channels accumulated per pass
#define IN_W 68       // smem input row stride (66 needed, pad to 68 for float4)
#define IN_H 18       // TY + 2 halo rows

__device__ __forceinline__ unsigned long long packf2(float lo, float hi) {
    unsigned long long r;
    asm("mov.b64 %0, {%1,%2};" : "=l"(r) : "f"(lo), "f"(hi));
    return r;
}
__device__ __forceinline__ void fma2(unsigned long long &d,
                                     unsigned long long a, unsigned long long b) {
    // d.lo += a.lo*b.lo ; d.hi += a.hi*b.hi   (packed fp32x2 FMA, sm_100+)
    asm("fma.rn.f32x2 %0, %1, %2, %0;" : "+l"(d) : "l"(a), "l"(b));
}
__device__ __forceinline__ float2 unpackf2(unsigned long long v) {
    float lo, hi;
    asm("mov.b64 {%0,%1}, %2;" : "=f"(lo), "=f"(hi) : "l"(v));
    return make_float2(lo, hi);
}

__global__ __launch_bounds__(TB)
void conv3x3_bias_scale_minC_kernel(const float* __restrict__ x,
                                    const float* __restrict__ w,
                                    const float* __restrict__ bias,
                                    float* __restrict__ out)
{
    __shared__ float s_in[ICC][IN_H][IN_W];   // 8*18*68*4 = 39168 B
    __shared__ float s_w[G][ICC][9];          // 2304 B

    const int b   = blockIdx.z;
    const int gx0 = blockIdx.x * TX;          // output-tile origin (also input origin)
    const int gy0 = blockIdx.y * TY;
    const int tid = threadIdx.x;
    const int tx  = tid & 15;                 // 16 thread cols * 4 px = 64
    const int ty  = tid >> 4;                 // 8 thread rows * 2 px = 16
    const int x0l = tx * 4;                   // local x of first pixel (0..60)
    const int y0l = ty * 2;                   // local y of first pixel (0..14)

    const float* xb = x + (size_t)b * C_ * H_ * W_;

    float m[2][4];
    #pragma unroll
    for (int r = 0; r < 2; r++)
        #pragma unroll
        for (int c = 0; c < 4; c++) m[r][c] = FLT_MAX;

    for (int og = 0; og < OC_; og += G) {
        // accumulators: [oc][out-row][x-pair]; init with bias (scale applied at end)
        unsigned long long acc[G][2][2];
        #pragma unroll
        for (int g = 0; g < G; g++) {
            float bv = __ldg(&bias[og + g]);
            unsigned long long bp = packf2(bv, bv);
            acc[g][0][0] = bp; acc[g][0][1] = bp;
            acc[g][1][0] = bp; acc[g][1][1] = bp;
        }

        for (int icc = 0; icc < C_; icc += ICC) {
            __syncthreads();   // previous chunk fully consumed
            // ---- stage input chunk (float4 granules, zero-padded halo) ----
            for (int idx = tid; idx < ICC * IN_H * 17; idx += TB) {
                int ic  = idx / (IN_H * 17);
                int rem = idx - ic * (IN_H * 17);
                int rr  = rem / 17;
                int j   = rem - rr * 17;
                int gy  = gy0 + rr;
                int gx  = gx0 + 4 * j;        // multiple of 4; OOB only as whole float4
                float4 v = make_float4(0.f, 0.f, 0.f, 0.f);
                if (gy < H_ && gx < W_) {
                    v = *reinterpret_cast<const float4*>(
                        xb + ((size_t)(icc + ic) * H_ + gy) * W_ + gx);
                }
                *reinterpret_cast<float4*>(&s_in[ic][rr][4 * j]) = v;
            }
            // ---- stage weights for (og-group, ic-chunk) ----
            for (int idx = tid; idx < G * ICC * 9; idx += TB) {
                int g   = idx / (ICC * 9);
                int rem = idx - g * (ICC * 9);
                int ic  = rem / 9;
                int k   = rem - ic * 9;
                s_w[g][ic][k] = w[((size_t)(og + g) * C_ + (icc + ic)) * 9 + k];
            }
            __syncthreads();

            for (int ic = 0; ic < ICC; ic++) {
                // P[r][k] = (in[r][x0l+k], in[r][x0l+k+1]); k = 2*pair + kx
                unsigned long long P[4][5];
                #pragma unroll
                for (int r = 0; r < 4; r++) {
                    const float* row = &s_in[ic][y0l + r][x0l];
                    float4 v = *reinterpret_cast<const float4*>(row);
                    float2 u = *reinterpret_cast<const float2*>(row + 4);
                    P[r][0] = packf2(v.x, v.y);
                    P[r][1] = packf2(v.y, v.z);
                    P[r][2] = packf2(v.z, v.w);
                    P[r][3] = packf2(v.w, u.x);
                    P[r][4] = packf2(u.x, u.y);
                }
                #pragma unroll
                for (int g = 0; g < G; g++) {
                    unsigned long long wp[9];
                    #pragma unroll
                    for (int k = 0; k < 9; k++) {
                        float wv = s_w[g][ic][k];     // broadcast LDS
                        wp[k] = packf2(wv, wv);
                    }
                    #pragma unroll
                    for (int r = 0; r < 2; r++)
                        #pragma unroll
                        for (int ky = 0; ky < 3; ky++)
                            #pragma unroll
                            for (int kx = 0; kx < 3; kx++)
                                #pragma unroll
                                for (int p = 0; p < 2; p++)
                                    fma2(acc[g][r][p],
                                         P[r + ky][2 * p + kx],
                                         wp[ky * 3 + kx]);
                }
            }
        }

        // fold this oc-group into the running channel-min
        #pragma unroll
        for (int g = 0; g < G; g++)
            #pragma unroll
            for (int r = 0; r < 2; r++)
                #pragma unroll
                for (int p = 0; p < 2; p++) {
                    float2 v = unpackf2(acc[g][r][p]);
                    m[r][2 * p]     = fminf(m[r][2 * p],     v.x);
                    m[r][2 * p + 1] = fminf(m[r][2 * p + 1], v.y);
                }
    }

    // y = (conv + bias) * 2; scale>0 commutes with min -> scale once here
    #pragma unroll
    for (int r = 0; r < 2; r++) {
        int oy = gy0 + y0l + r;
        if (oy >= OH_) continue;
        #pragma unroll
        for (int c = 0; c < 4; c++) {
            int ox = gx0 + x0l + c;
            if (ox >= OW_) continue;
            out[((size_t)b * OH_ + oy) * OW_ + ox] = 2.0f * m[r][c];
        }
    }
}

extern "C" void kernel_launch(void* const* d_in, const int* in_sizes, int n_in,
                              void* d_out, int out_size)
{
    const float* x    = (const float*)d_in[0];   // (16,64,256,256)
    const float* w    = (const float*)d_in[1];   // (128,64,3,3)
    const float* bias = (const float*)d_in[2];   // (128,)
    float* out = (float*)d_out;                  // (16,1,254,254)

    dim3 grid((OW_ + TX - 1) / TX,   // 4
              (OH_ + TY - 1) / TY,   // 16
              B_);                   // 16
    conv3x3_bias_scale_minC_kernel<<<grid, TB>>>(x, w, bias, out);
    (void)in_sizes; (void)n_in; (void)out_size;
}

// round 5
// speedup vs baseline: 1.0001x; 1.0001x over previous
#include <cuda_runtime.h>
#include <float.h>

// Problem constants
#define B_   16
#define C_   64
#define H_   256
#define W_   256
#define OC_  128
#define OH_  254
#define OW_  254

// Tiling
#define TB   128      // threads per block
#define TX   64       // output tile width
#define TY   16       // output tile height
#define ICC  8        // input-channel chunk staged in smem
#define G    8        // output channels accumulated per pass
#define IN_W 68       // smem input row stride (66 needed, pad to 68 for float4)
#define IN_H 18       // TY + 2 halo rows

__device__ __forceinline__ unsigned long long packf2(float lo, float hi) {
    unsigned long long r;
    asm("mov.b64 %0, {%1,%2};" : "=l"(r) : "f"(lo), "f"(hi));
    return r;
}
__device__ __forceinline__ void fma2(unsigned long long &d,
                                     unsigned long long a, unsigned long long b) {
    // d.lo += a.lo*b.lo ; d.hi += a.hi*b.hi   (packed fp32x2 FMA, sm_100+)
    asm("fma.rn.f32x2 %0, %1, %2, %0;" : "+l"(d) : "l"(a), "l"(b));
}
__device__ __forceinline__ float2 unpackf2(unsigned long long v) {
    float lo, hi;
    asm("mov.b64 {%0,%1}, %2;" : "=f"(lo), "=f"(hi) : "l"(v));
    return make_float2(lo, hi);
}

__global__ __launch_bounds__(TB)
void conv3x3_bias_scale_minC_kernel(const float* __restrict__ x,
                                    const float* __restrict__ w,
                                    const float* __restrict__ bias,
                                    float* __restrict__ out)
{
    __shared__ float s_in[ICC][IN_H][IN_W];   // 8*18*68*4 = 39168 B
    __shared__ float s_w[G][ICC][9];          // 2304 B

    const int b   = blockIdx.z;
    const int gx0 = blockIdx.x * TX;          // output-tile origin (also input origin)
    const int gy0 = blockIdx.y * TY;
    const int tid = threadIdx.x;
    const int tx  = tid & 15;                 // 16 thread cols * 4 px = 64
    const int ty  = tid >> 4;                 // 8 thread rows * 2 px = 16
    const int x0l = tx * 4;                   // local x of first pixel (0..60)
    const int y0l = ty * 2;                   // local y of first pixel (0..14)

    const float* xb = x + (size_t)b * C_ * H_ * W_;

    float m[2][4];
    #pragma unroll
    for (int r = 0; r < 2; r++)
        #pragma unroll
        for (int c = 0; c < 4; c++) m[r][c] = FLT_MAX;

    for (int og = 0; og < OC_; og += G) {
        // accumulators: [oc][out-row][x-pair]; init with bias (scale applied at end)
        unsigned long long acc[G][2][2];
        #pragma unroll
        for (int g = 0; g < G; g++) {
            float bv = __ldg(&bias[og + g]);
            unsigned long long bp = packf2(bv, bv);
            acc[g][0][0] = bp; acc[g][0][1] = bp;
            acc[g][1][0] = bp; acc[g][1][1] = bp;
        }

        for (int icc = 0; icc < C_; icc += ICC) {
            __syncthreads();   // previous chunk fully consumed
            // ---- stage input chunk (float4 granules, zero-padded halo) ----
            for (int idx = tid; idx < ICC * IN_H * 17; idx += TB) {
                int ic  = idx / (IN_H * 17);
                int rem = idx - ic * (IN_H * 17);
                int rr  = rem / 17;
                int j   = rem - rr * 17;
                int gy  = gy0 + rr;
                int gx  = gx0 + 4 * j;        // multiple of 4; OOB only as whole float4
                float4 v = make_float4(0.f, 0.f, 0.f, 0.f);
                if (gy < H_ && gx < W_) {
                    v = *reinterpret_cast<const float4*>(
                        xb + ((size_t)(icc + ic) * H_ + gy) * W_ + gx);
                }
                *reinterpret_cast<float4*>(&s_in[ic][rr][4 * j]) = v;
            }
            // ---- stage weights for (og-group, ic-chunk) ----
            for (int idx = tid; idx < G * ICC * 9; idx += TB) {
                int g   = idx / (ICC * 9);
                int rem = idx - g * (ICC * 9);
                int ic  = rem / 9;
                int k   = rem - ic * 9;
                s_w[g][ic][k] = w[((size_t)(og + g) * C_ + (icc + ic)) * 9 + k];
            }
            __syncthreads();

            for (int ic = 0; ic < ICC; ic++) {
                // P[r][k] = (in[r][x0l+k], in[r][x0l+k+1]); k = 2*pair + kx
                unsigned long long P[4][5];
                #pragma unroll
                for (int r = 0; r < 4; r++) {
                    const float* row = &s_in[ic][y0l + r][x0l];
                    float4 v = *reinterpret_cast<const float4*>(row);
                    float2 u = *reinterpret_cast<const float2*>(row + 4);
                    P[r][0] = packf2(v.x, v.y);
                    P[r][1] = packf2(v.y, v.z);
                    P[r][2] = packf2(v.z, v.w);
                    P[r][3] = packf2(v.w, u.x);
                    P[r][4] = packf2(u.x, u.y);
                }
                #pragma unroll
                for (int g = 0; g < G; g++) {
                    unsigned long long wp[9];
                    #pragma unroll
                    for (int k = 0; k < 9; k++) {
                        float wv = s_w[g][ic][k];     // broadcast LDS
                        wp[k] = packf2(wv, wv);
                    }
                    #pragma unroll
                    for (int r = 0; r < 2; r++)
                        #pragma unroll
                        for (int ky = 0; ky < 3; ky++)
                            #pragma unroll
                            for (int kx = 0; kx < 3; kx++)
                                #pragma unroll
                                for (int p = 0; p < 2; p++)
                                    fma2(acc[g][r][p],
                                         P[r + ky][2 * p + kx],
                                         wp[ky * 3 + kx]);
                }
            }
        }

        // fold this oc-group into the running channel-min
        #pragma unroll
        for (int g = 0; g < G; g++)
            #pragma unroll
            for (int r = 0; r < 2; r++)
                #pragma unroll
                for (int p = 0; p < 2; p++) {
                    float2 v = unpackf2(acc[g][r][p]);
                    m[r][2 * p]     = fminf(m[r][2 * p],     v.x);
                    m[r][2 * p + 1] = fminf(m[r][2 * p + 1], v.y);
                }
    }

    // y = (conv + bias) * 2; scale>0 commutes with min -> scale once here
    #pragma unroll
    for (int r = 0; r < 2; r++) {
        int oy = gy0 + y0l + r;
        if (oy >= OH_) continue;
        #pragma unroll
        for (int c = 0; c < 4; c++) {
            int ox = gx0 + x0l + c;
            if (ox >= OW_) continue;
            out[((size_t)b * OH_ + oy) * OW_ + ox] = 2.0f * m[r][c];
        }
    }
}

extern "C" void kernel_launch(void* const* d_in, const int* in_sizes, int n_in,
                              void* d_out, int out_size)
{
    const float* x    = (const float*)d_in[0];   // (16,64,256,256)
    const float* w    = (const float*)d_in[1];   // (128,64,3,3)
    const float* bias = (const float*)d_in[2];   // (128,)
    float* out = (float*)d_out;                  // (16,1,254,254)

    dim3 grid((OW_ + TX - 1) / TX,   // 4
              (OH_ + TY - 1) / TY,   // 16
              B_);                   // 16
    conv3x3_bias_scale_minC_kernel<<<grid, TB>>>(x, w, bias, out);
    (void)in_sizes; (void)n_in; (void)out_size;
}